// round 8
// baseline (speedup 1.0000x reference)
#include <cuda_runtime.h>
#include <cuda_fp16.h>
#include <cstdint>

// ===================== problem constants =====================
#define BATCH_ 8192
#define O_     8
#define K_     2048      // N*U
#define V_     256

// ===================== GEMM tiling =====================
#define BM 128
#define BN 128
#define BK 32
#define NSTG 4
#define ROWB 80          // padded smem row: 32 halves + 16B pad
#define A_BYTES (BM * ROWB)            // 10240
#define B_BYTES (BN * ROWB)            // 10240
#define STG_BYTES (A_BYTES + B_BYTES)  // 20480
#define SMEM_TOTAL (NSTG * STG_BYTES)  // 81920

// ===================== scratch =====================
__device__ __half g_xh[(size_t)BATCH_ * K_];   // fp16 X (active n-slices only)
__device__ __half g_wh[(size_t)O_ * V_ * K_];  // gated, transposed fp16 W [o][v][k]

// ===================== helpers =====================
__device__ __forceinline__ uint32_t smem_u32(const void* p) {
    uint32_t a;
    asm("{ .reg .u64 t; cvta.to.shared.u64 t, %1; cvt.u32.u64 %0, t; }" : "=r"(a) : "l"(p));
    return a;
}
__device__ __forceinline__ void cpa16(uint32_t d, const void* g) {
    asm volatile("cp.async.cg.shared.global [%0], [%1], 16;" :: "r"(d), "l"(g));
}
#define CP_COMMIT() asm volatile("cp.async.commit_group;" ::: "memory")
#define CP_WAIT2()  asm volatile("cp.async.wait_group 2;" ::: "memory")

__device__ __forceinline__ void ldsm4(uint32_t (&r)[4], uint32_t addr) {
    asm volatile("ldmatrix.sync.aligned.m8n8.x4.shared.b16 {%0,%1,%2,%3}, [%4];"
                 : "=r"(r[0]), "=r"(r[1]), "=r"(r[2]), "=r"(r[3]) : "r"(addr));
}
__device__ __forceinline__ void mma16816(float* c, const uint32_t* a,
                                         uint32_t b0, uint32_t b1) {
    asm volatile(
        "mma.sync.aligned.m16n8k16.row.col.f32.f16.f16.f32 "
        "{%0,%1,%2,%3}, {%4,%5,%6,%7}, {%8,%9}, {%0,%1,%2,%3};"
        : "+f"(c[0]), "+f"(c[1]), "+f"(c[2]), "+f"(c[3])
        : "r"(a[0]), "r"(a[1]), "r"(a[2]), "r"(a[3]), "r"(b0), "r"(b1));
}

// fast-math gate (identical everywhere -> consistent open/closed decisions)
__device__ __forceinline__ float gate_z(const float* u_param, const float* alpha, int idx) {
    float uu = u_param[idx];
    float s = __logf(uu) - __logf(1.0f - uu) + __logf(alpha[0]) * (1.0f / 0.9f);
    s = 1.0f / (1.0f + __expf(-s));
    float z = s * 1.2f - 0.1f;
    return fminf(fmaxf(z, 0.0f), 1.0f);
}

// ===================== prepass (one kernel, 4096 blocks) =====================
// [0, 2048):    X -> fp16 for active-n slices (4 b-rows per block)
// [2048, 3072): gate-scaled W transpose for open gates
// [3072, 4096): zero-fill of out for INACTIVE o columns (64 b-rows per block)
__global__ void prep(const float* __restrict__ X,
                     const float* __restrict__ T,
                     const float* __restrict__ alpha,
                     const float* __restrict__ u_param,
                     float* __restrict__ out) {
    __shared__ float zs[64];
    __shared__ int actn[8];
    int tid = threadIdx.x;
    if (tid < 64) zs[tid] = gate_z(u_param, alpha, tid);
    __syncthreads();

    if (blockIdx.x < 2048) {
        // ---- X conversion, active-n only ----
        if (tid < 8) {
            int a = 0;
#pragma unroll
            for (int o = 0; o < 8; o++) a |= (zs[o * 8 + tid] > 0.0f);
            actn[tid] = a;
        }
        __syncthreads();
        int b  = (blockIdx.x << 2) + (tid >> 6);
        int u4 = tid & 63;
#pragma unroll
        for (int n = 0; n < 8; n++) {
            if (!actn[n]) continue;
            size_t e = ((size_t)b * 8 + n) * 256 + u4 * 4;
            float4 v = *reinterpret_cast<const float4*>(X + e);
            __half2 h0 = __floats2half2_rn(v.x, v.y);
            __half2 h1 = __floats2half2_rn(v.z, v.w);
            uint2 w;
            w.x = *reinterpret_cast<uint32_t*>(&h0);
            w.y = *reinterpret_cast<uint32_t*>(&h1);
            *reinterpret_cast<uint2*>(g_xh + e) = w;
        }
        return;
    }

    if (blockIdx.x < 3072) {
        // ---- W gate + transpose, open gates only ----
        __shared__ float tile[64][65];
        int blk = blockIdx.x - 2048;   // 0..1023
        int on = blk >> 4;
        int o = on >> 3, n = on & 7;
        int u0 = ((blk >> 2) & 3) * 64;
        int v0 = (blk & 3) * 64;
        float z = zs[o * 8 + n];
        if (z == 0.0f) return;

        const float* tb = T + (((size_t)(o * 8 + n) * 256 + u0) * 256 + v0);
#pragma unroll
        for (int i = 0; i < 16; i++) {
            int r = i * 4 + (tid >> 6);
            int c = tid & 63;
            tile[r][c] = tb[(size_t)r * 256 + c];
        }
        __syncthreads();

        __half* wb = g_wh + ((size_t)o * 256 + v0) * 2048 + n * 256 + u0;
#pragma unroll
        for (int i = 0; i < 16; i++) {
            int r = i * 4 + (tid >> 6);   // v-row
            int c = tid & 63;             // u-col
            wb[(size_t)r * 2048 + c] = __float2half_rn(tile[c][r] * z);
        }
        return;
    }

    // ---- zero-fill for inactive o (high occupancy; 64KB per block) ----
    {
        int blk = blockIdx.x - 3072;    // 0..1023
        int o = blk >> 7;               // 128 blocks per o
        int active = 0;
#pragma unroll
        for (int nn = 0; nn < 8; nn++) active |= (zs[o * 8 + nn] > 0.0f);
        if (active) return;             // gemm writes this o

        int b0 = (blk & 127) << 6;      // 64 b-rows per block
        int row = tid >> 2;             // 64 rows, 4 threads each
        int q0  = (tid & 3) * 16;       // 16 uint4 = 256B per thread
        uint4* p = reinterpret_cast<uint4*>(
            out + ((size_t)(b0 + row) * O_ + o) * V_) + q0;
        const uint4 z4 = make_uint4(0u, 0u, 0u, 0u);
#pragma unroll
        for (int j = 0; j < 16; j++) __stwt(p + j, z4);
    }
}

// ===================== fp16 pipelined GEMM (active o only) =====================
// Grid (16, 64): x = (o, n-half), y = m-tile. 256 threads = 8 warps (4m x 2n).
__global__ __launch_bounds__(256)
void gemm_fp16(const float* __restrict__ alpha,
               const float* __restrict__ u_param,
               float* __restrict__ out) {
    extern __shared__ char smem[];
    const uint32_t sb = smem_u32(smem);
    __shared__ float zs[64];
    __shared__ int nlist_s[8];
    __shared__ int cnt_s;

    const int tid = threadIdx.x, lane = tid & 31, warp = tid >> 5;
    const int o  = blockIdx.x >> 1;
    const int n0 = (blockIdx.x & 1) * BN;
    const int m0 = blockIdx.y * BM;

    if (tid < 64) zs[tid] = gate_z(u_param, alpha, tid);
    __syncthreads();
    if (tid == 0) {
        int c = 0;
#pragma unroll
        for (int nn = 0; nn < 8; nn++)
            if (zs[o * 8 + nn] > 0.0f) nlist_s[c++] = nn;
        cnt_s = c;
    }
    __syncthreads();
    const int chunks = cnt_s * 8;
    if (chunks == 0) return;          // prep zero-filled this o

    const __half* Ag = g_xh + (size_t)m0 * K_;
    const __half* Bg = g_wh + ((size_t)o * V_ + n0) * K_;

    const int i0 = tid * 2;
    const int r0 = i0 >> 2, c0 = i0 & 3;
    const int r1 = (i0 + 1) >> 2, c1 = (i0 + 1) & 3;

    auto issue = [&](int c) {
        const uint32_t so = (uint32_t)(c & 3) * STG_BYTES;
        const int k0 = (nlist_s[c >> 3] << 8) + ((c & 7) << 5);
        cpa16(sb + so + r0 * ROWB + c0 * 16,           Ag + (size_t)r0 * K_ + k0 + c0 * 8);
        cpa16(sb + so + r1 * ROWB + c1 * 16,           Ag + (size_t)r1 * K_ + k0 + c1 * 8);
        cpa16(sb + so + A_BYTES + r0 * ROWB + c0 * 16, Bg + (size_t)r0 * K_ + k0 + c0 * 8);
        cpa16(sb + so + A_BYTES + r1 * ROWB + c1 * 16, Bg + (size_t)r1 * K_ + k0 + c1 * 8);
    };

    const int mo = (warp >> 1) * 32;
    const int no = (warp & 1) * 64;
    uint32_t a_addr[2], b_addr[4];
    {
        const int arl = lane & 15;
        const int akh = (lane >> 4) & 1;
#pragma unroll
        for (int mf = 0; mf < 2; mf++)
            a_addr[mf] = sb + (mo + mf * 16 + arl) * ROWB + akh * 16;
        const int brl = (lane & 7) + ((lane >> 4) & 1) * 8;
        const int bkh = (lane >> 3) & 1;
#pragma unroll
        for (int p = 0; p < 4; p++)
            b_addr[p] = sb + A_BYTES + (no + p * 16 + brl) * ROWB + bkh * 16;
    }

    float acc[2][8][4];
#pragma unroll
    for (int i = 0; i < 2; i++)
#pragma unroll
        for (int j = 0; j < 8; j++)
#pragma unroll
            for (int k = 0; k < 4; k++) acc[i][j][k] = 0.0f;

#pragma unroll
    for (int p = 0; p < 3; p++) {
        if (p < chunks) issue(p);
        CP_COMMIT();
    }

    for (int c = 0; c < chunks; ++c) {
        CP_WAIT2();
        __syncthreads();
        if (c + 3 < chunks) issue(c + 3);
        CP_COMMIT();

        const uint32_t so = (uint32_t)(c & 3) * STG_BYTES;
#pragma unroll
        for (int ks = 0; ks < 2; ks++) {
            const uint32_t kb = so + ks * 32;
            uint32_t a[2][4], b[4][4];
#pragma unroll
            for (int mf = 0; mf < 2; mf++) ldsm4(a[mf], a_addr[mf] + kb);
#pragma unroll
            for (int p = 0; p < 4; p++) ldsm4(b[p], b_addr[p] + kb);
#pragma unroll
            for (int mf = 0; mf < 2; mf++)
#pragma unroll
                for (int p = 0; p < 4; p++) {
                    mma16816(acc[mf][2 * p],     a[mf], b[p][0], b[p][1]);
                    mma16816(acc[mf][2 * p + 1], a[mf], b[p][2], b[p][3]);
                }
        }
        __syncthreads();
    }

    const int gid = lane >> 2, tig = lane & 3;
#pragma unroll
    for (int mf = 0; mf < 2; mf++) {
        const int brow = m0 + mo + mf * 16 + gid;
#pragma unroll
        for (int nb = 0; nb < 8; nb++) {
            const int v = n0 + no + nb * 8 + tig * 2;
            float* c = acc[mf][nb];
            __stwt(reinterpret_cast<float2*>(
                out + ((size_t)brow * O_ + o) * V_ + v), make_float2(c[0], c[1]));
            __stwt(reinterpret_cast<float2*>(
                out + ((size_t)(brow + 8) * O_ + o) * V_ + v), make_float2(c[2], c[3]));
        }
    }
}

// ===================== host =====================
extern "C" void kernel_launch(void* const* d_in, const int* in_sizes, int n_in,
                              void* d_out, int out_size) {
    const float* x = nullptr, *alpha = nullptr, *u = nullptr, *T = nullptr;
    for (int i = 0; i < n_in; i++) {
        switch (in_sizes[i]) {
            case 16777216: x     = (const float*)d_in[i]; break;
            case 1:        alpha = (const float*)d_in[i]; break;
            case 64:       u     = (const float*)d_in[i]; break;
            case 4194304:  T     = (const float*)d_in[i]; break;
        }
    }
    if (!x || !alpha || !u || !T) return;
    float* out = (float*)d_out;

    static bool attr_set = false;
    if (!attr_set) {
        cudaFuncSetAttribute(gemm_fp16, cudaFuncAttributeMaxDynamicSharedMemorySize,
                             SMEM_TOTAL);
        attr_set = true;
    }

    prep<<<4096, 256>>>(x, T, alpha, u, out);
    gemm_fp16<<<dim3(16, 64), 256, SMEM_TOTAL>>>(alpha, u, out);
}

// round 9
// speedup vs baseline: 1.4300x; 1.4300x over previous
#include <cuda_runtime.h>
#include <cuda_fp16.h>
#include <cstdint>

// ===================== problem constants =====================
#define BATCH_ 8192
#define O_     8
#define K_     2048      // N*U
#define V_     256

// ===================== GEMM tiling =====================
#define BM 128
#define BN 128
#define BK 64            // halves per pipeline chunk (128B per row)
#define NSTG 3
#define ROWB 144         // 128B data + 16B pad (conflict-free ldmatrix)
#define A_BYTES (BM * ROWB)            // 18432
#define B_BYTES (BN * ROWB)            // 18432
#define STG_BYTES (A_BYTES + B_BYTES)  // 36864
#define SMEM_TOTAL (NSTG * STG_BYTES)  // 110592

// ===================== scratch =====================
__device__ __half g_xh[(size_t)BATCH_ * K_];   // fp16 X (active n-slices only)
__device__ __half g_wh[(size_t)O_ * V_ * K_];  // gated, transposed fp16 W [o][v][k]

// ===================== helpers =====================
__device__ __forceinline__ uint32_t smem_u32(const void* p) {
    uint32_t a;
    asm("{ .reg .u64 t; cvta.to.shared.u64 t, %1; cvt.u32.u64 %0, t; }" : "=r"(a) : "l"(p));
    return a;
}
__device__ __forceinline__ void cpa16(uint32_t d, const void* g) {
    asm volatile("cp.async.cg.shared.global [%0], [%1], 16;" :: "r"(d), "l"(g));
}
#define CP_COMMIT() asm volatile("cp.async.commit_group;" ::: "memory")
#define CP_WAIT1()  asm volatile("cp.async.wait_group 1;" ::: "memory")

__device__ __forceinline__ void ldsm4(uint32_t (&r)[4], uint32_t addr) {
    asm volatile("ldmatrix.sync.aligned.m8n8.x4.shared.b16 {%0,%1,%2,%3}, [%4];"
                 : "=r"(r[0]), "=r"(r[1]), "=r"(r[2]), "=r"(r[3]) : "r"(addr));
}
__device__ __forceinline__ void mma16816(float* c, const uint32_t* a,
                                         uint32_t b0, uint32_t b1) {
    asm volatile(
        "mma.sync.aligned.m16n8k16.row.col.f32.f16.f16.f32 "
        "{%0,%1,%2,%3}, {%4,%5,%6,%7}, {%8,%9}, {%0,%1,%2,%3};"
        : "+f"(c[0]), "+f"(c[1]), "+f"(c[2]), "+f"(c[3])
        : "r"(a[0]), "r"(a[1]), "r"(a[2]), "r"(a[3]), "r"(b0), "r"(b1));
}

// fast-math gate (identical everywhere -> consistent open/closed decisions)
__device__ __forceinline__ float gate_z(const float* u_param, const float* alpha, int idx) {
    float uu = u_param[idx];
    float s = __logf(uu) - __logf(1.0f - uu) + __logf(alpha[0]) * (1.0f / 0.9f);
    s = 1.0f / (1.0f + __expf(-s));
    float z = s * 1.2f - 0.1f;
    return fminf(fmaxf(z, 0.0f), 1.0f);
}

// ===================== prepass (3072 blocks) =====================
// [0, 2048):    X -> fp16 for active-n slices (4 b-rows per block)
// [2048, 3072): gate-scaled W transpose for open gates
__global__ void prep(const float* __restrict__ X,
                     const float* __restrict__ T,
                     const float* __restrict__ alpha,
                     const float* __restrict__ u_param) {
    __shared__ float zs[64];
    __shared__ int actn[8];
    int tid = threadIdx.x;
    if (tid < 64) zs[tid] = gate_z(u_param, alpha, tid);
    __syncthreads();

    if (blockIdx.x < 2048) {
        if (tid < 8) {
            int a = 0;
#pragma unroll
            for (int o = 0; o < 8; o++) a |= (zs[o * 8 + tid] > 0.0f);
            actn[tid] = a;
        }
        __syncthreads();
        int b  = (blockIdx.x << 2) + (tid >> 6);
        int u4 = tid & 63;
#pragma unroll
        for (int n = 0; n < 8; n++) {
            if (!actn[n]) continue;
            size_t e = ((size_t)b * 8 + n) * 256 + u4 * 4;
            float4 v = *reinterpret_cast<const float4*>(X + e);
            __half2 h0 = __floats2half2_rn(v.x, v.y);
            __half2 h1 = __floats2half2_rn(v.z, v.w);
            uint2 w;
            w.x = *reinterpret_cast<uint32_t*>(&h0);
            w.y = *reinterpret_cast<uint32_t*>(&h1);
            *reinterpret_cast<uint2*>(g_xh + e) = w;
        }
        return;
    }

    // ---- W gate + transpose, open gates only ----
    __shared__ float tile[64][65];
    int blk = blockIdx.x - 2048;   // 0..1023
    int on = blk >> 4;
    int o = on >> 3, n = on & 7;
    int u0 = ((blk >> 2) & 3) * 64;
    int v0 = (blk & 3) * 64;
    float z = zs[o * 8 + n];
    if (z == 0.0f) return;

    const float* tb = T + (((size_t)(o * 8 + n) * 256 + u0) * 256 + v0);
#pragma unroll
    for (int i = 0; i < 16; i++) {
        int r = i * 4 + (tid >> 6);
        int c = tid & 63;
        tile[r][c] = tb[(size_t)r * 256 + c];
    }
    __syncthreads();

    __half* wb = g_wh + ((size_t)o * 256 + v0) * 2048 + n * 256 + u0;
#pragma unroll
    for (int i = 0; i < 16; i++) {
        int r = i * 4 + (tid >> 6);   // v-row
        int c = tid & 63;             // u-col
        wb[(size_t)r * 2048 + c] = __float2half_rn(tile[c][r] * z);
    }
}

// ===================== fp16 pipelined GEMM =====================
// Grid (16, 64): x = (o, n-half), y = m-tile. 256 threads = 8 warps (4m x 2n).
// BK=64 per iteration; 3-stage cp.async, depth-2 prefetch, single sync per iter.
__global__ __launch_bounds__(256)
void gemm_fp16(const float* __restrict__ alpha,
               const float* __restrict__ u_param,
               float* __restrict__ out) {
    extern __shared__ char smem[];
    const uint32_t sb = smem_u32(smem);
    __shared__ float zs[64];
    __shared__ int nlist_s[8];
    __shared__ int cnt_s;

    const int tid = threadIdx.x, lane = tid & 31, warp = tid >> 5;
    const int o  = blockIdx.x >> 1;
    const int n0 = (blockIdx.x & 1) * BN;
    const int m0 = blockIdx.y * BM;

    if (tid < 64) zs[tid] = gate_z(u_param, alpha, tid);
    __syncthreads();
    if (tid == 0) {
        int c = 0;
#pragma unroll
        for (int nn = 0; nn < 8; nn++)
            if (zs[o * 8 + nn] > 0.0f) nlist_s[c++] = nn;
        cnt_s = c;
    }
    __syncthreads();
    const int chunks = cnt_s * 4;     // 4 x BK=64 chunks per active n

    // ---- fast path: closed o -> coalesced write-through zeros (overlaps fine) ----
    if (chunks == 0) {
        float* base = out + ((size_t)m0 * O_ + o) * V_ + n0;
        const uint4 z4 = make_uint4(0u, 0u, 0u, 0u);
#pragma unroll
        for (int i = tid; i < 4096; i += 256) {       // 128 rows x 32 uint4
            int r = i >> 5, c = i & 31;
            __stwt(reinterpret_cast<uint4*>(base + (size_t)r * (O_ * V_)) + c, z4);
        }
        return;
    }

    const __half* Ag = g_xh + (size_t)m0 * K_;
    const __half* Bg = g_wh + ((size_t)o * V_ + n0) * K_;

    // cp.async: 1024 A ops + 1024 B ops per stage, 8 per thread
    auto issue = [&](int c) {
        const uint32_t so = (uint32_t)(c % 3) * STG_BYTES;
        const int k0 = (nlist_s[c >> 2] << 8) + ((c & 3) << 6);
#pragma unroll
        for (int i = 0; i < 4; i++) {
            int idx = tid + i * 256;
            int r = idx >> 3, cc = idx & 7;
            cpa16(sb + so + r * ROWB + cc * 16, Ag + (size_t)r * K_ + k0 + cc * 8);
        }
#pragma unroll
        for (int i = 0; i < 4; i++) {
            int idx = tid + i * 256;
            int r = idx >> 3, cc = idx & 7;
            cpa16(sb + so + A_BYTES + r * ROWB + cc * 16,
                  Bg + (size_t)r * K_ + k0 + cc * 8);
        }
    };

    const int mo = (warp >> 1) * 32;
    const int no = (warp & 1) * 64;
    uint32_t a_addr[2], b_addr[4];
    {
        const int arl = lane & 15;
        const int akh = (lane >> 4) & 1;
#pragma unroll
        for (int mf = 0; mf < 2; mf++)
            a_addr[mf] = sb + (mo + mf * 16 + arl) * ROWB + akh * 16;
        const int brl = (lane & 7) + ((lane >> 4) & 1) * 8;
        const int bkh = (lane >> 3) & 1;
#pragma unroll
        for (int p = 0; p < 4; p++)
            b_addr[p] = sb + A_BYTES + (no + p * 16 + brl) * ROWB + bkh * 16;
    }

    float acc[2][8][4];
#pragma unroll
    for (int i = 0; i < 2; i++)
#pragma unroll
        for (int j = 0; j < 8; j++)
#pragma unroll
            for (int k = 0; k < 4; k++) acc[i][j][k] = 0.0f;

    issue(0); CP_COMMIT();
    if (chunks > 1) issue(1);
    CP_COMMIT();

    for (int c = 0; c < chunks; ++c) {
        CP_WAIT1();               // group c complete (<=1 pending)
        __syncthreads();          // orders all reads of stage (c-? ) / writes of c+2
        if (c + 2 < chunks) issue(c + 2);
        CP_COMMIT();

        const uint32_t so = (uint32_t)(c % 3) * STG_BYTES;
#pragma unroll
        for (int ks = 0; ks < 4; ks++) {       // 4 k16 steps per BK=64
            const uint32_t kb = so + ks * 32;  // 16 halves = 32 bytes
            uint32_t a[2][4], b[4][4];
#pragma unroll
            for (int mf = 0; mf < 2; mf++) ldsm4(a[mf], a_addr[mf] + kb);
#pragma unroll
            for (int p = 0; p < 4; p++) ldsm4(b[p], b_addr[p] + kb);
#pragma unroll
            for (int mf = 0; mf < 2; mf++)
#pragma unroll
                for (int p = 0; p < 4; p++) {
                    mma16816(acc[mf][2 * p],     a[mf], b[p][0], b[p][1]);
                    mma16816(acc[mf][2 * p + 1], a[mf], b[p][2], b[p][3]);
                }
        }
        // no bottom sync: top sync of iter c+1 guards stage reuse (3 stages, depth 2)
    }

    const int gid = lane >> 2, tig = lane & 3;
#pragma unroll
    for (int mf = 0; mf < 2; mf++) {
        const int brow = m0 + mo + mf * 16 + gid;
#pragma unroll
        for (int nb = 0; nb < 8; nb++) {
            const int v = n0 + no + nb * 8 + tig * 2;
            float* c = acc[mf][nb];
            __stwt(reinterpret_cast<float2*>(
                out + ((size_t)brow * O_ + o) * V_ + v), make_float2(c[0], c[1]));
            __stwt(reinterpret_cast<float2*>(
                out + ((size_t)(brow + 8) * O_ + o) * V_ + v), make_float2(c[2], c[3]));
        }
    }
}

// ===================== host =====================
extern "C" void kernel_launch(void* const* d_in, const int* in_sizes, int n_in,
                              void* d_out, int out_size) {
    const float* x = nullptr, *alpha = nullptr, *u = nullptr, *T = nullptr;
    for (int i = 0; i < n_in; i++) {
        switch (in_sizes[i]) {
            case 16777216: x     = (const float*)d_in[i]; break;
            case 1:        alpha = (const float*)d_in[i]; break;
            case 64:       u     = (const float*)d_in[i]; break;
            case 4194304:  T     = (const float*)d_in[i]; break;
        }
    }
    if (!x || !alpha || !u || !T) return;
    float* out = (float*)d_out;

    static bool attr_set = false;
    if (!attr_set) {
        cudaFuncSetAttribute(gemm_fp16, cudaFuncAttributeMaxDynamicSharedMemorySize,
                             SMEM_TOTAL);
        attr_set = true;
    }

    prep<<<3072, 256>>>(x, T, alpha, u);
    gemm_fp16<<<dim3(16, 64), 256, SMEM_TOTAL>>>(alpha, u, out);
}

// round 10
// speedup vs baseline: 1.5487x; 1.0830x over previous
#include <cuda_runtime.h>
#include <cuda_fp16.h>
#include <cstdint>

// ===================== problem constants =====================
#define BATCH_ 8192
#define O_     8
#define K_     2048      // N*U
#define V_     256

// ===================== GEMM tiling =====================
#define BM 64
#define BN 128
#define BK 64            // halves per pipeline chunk (128B per row)
#define NSTG 2
#define ROWB 144         // 128B data + 16B pad (conflict-free ldmatrix)
#define A_BYTES (BM * ROWB)            // 9216
#define B_BYTES (BN * ROWB)            // 18432
#define STG_BYTES (A_BYTES + B_BYTES)  // 27648
#define SMEM_TOTAL (NSTG * STG_BYTES)  // 55296 -> 4 CTAs/SM

// ===================== scratch =====================
__device__ __half g_xh[(size_t)BATCH_ * K_];   // fp16 X (active n-slices only)
__device__ __half g_wh[(size_t)O_ * V_ * K_];  // gated, transposed fp16 W [o][v][k]

// ===================== helpers =====================
__device__ __forceinline__ uint32_t smem_u32(const void* p) {
    uint32_t a;
    asm("{ .reg .u64 t; cvta.to.shared.u64 t, %1; cvt.u32.u64 %0, t; }" : "=r"(a) : "l"(p));
    return a;
}
__device__ __forceinline__ void cpa16(uint32_t d, const void* g) {
    asm volatile("cp.async.cg.shared.global [%0], [%1], 16;" :: "r"(d), "l"(g));
}
#define CP_COMMIT() asm volatile("cp.async.commit_group;" ::: "memory")
#define CP_WAIT1()  asm volatile("cp.async.wait_group 1;" ::: "memory")

__device__ __forceinline__ void ldsm4(uint32_t (&r)[4], uint32_t addr) {
    asm volatile("ldmatrix.sync.aligned.m8n8.x4.shared.b16 {%0,%1,%2,%3}, [%4];"
                 : "=r"(r[0]), "=r"(r[1]), "=r"(r[2]), "=r"(r[3]) : "r"(addr));
}
__device__ __forceinline__ void mma16816(float* c, const uint32_t* a,
                                         uint32_t b0, uint32_t b1) {
    asm volatile(
        "mma.sync.aligned.m16n8k16.row.col.f32.f16.f16.f32 "
        "{%0,%1,%2,%3}, {%4,%5,%6,%7}, {%8,%9}, {%0,%1,%2,%3};"
        : "+f"(c[0]), "+f"(c[1]), "+f"(c[2]), "+f"(c[3])
        : "r"(a[0]), "r"(a[1]), "r"(a[2]), "r"(a[3]), "r"(b0), "r"(b1));
}

// fast-math gate (identical everywhere -> consistent open/closed decisions)
__device__ __forceinline__ float gate_z(const float* u_param, const float* alpha, int idx) {
    float uu = u_param[idx];
    float s = __logf(uu) - __logf(1.0f - uu) + __logf(alpha[0]) * (1.0f / 0.9f);
    s = 1.0f / (1.0f + __expf(-s));
    float z = s * 1.2f - 0.1f;
    return fminf(fmaxf(z, 0.0f), 1.0f);
}

// ===================== prepass (3072 blocks, 256 threads) =====================
// [0, 2048):    X -> fp16 for active-n slices (4 b-rows per block)
// [2048, 3072): gate-scaled W transpose for open gates
__global__ void prep(const float* __restrict__ X,
                     const float* __restrict__ T,
                     const float* __restrict__ alpha,
                     const float* __restrict__ u_param) {
    __shared__ float zs[64];
    __shared__ int actn[8];
    int tid = threadIdx.x;
    if (tid < 64) zs[tid] = gate_z(u_param, alpha, tid);
    __syncthreads();

    if (blockIdx.x < 2048) {
        if (tid < 8) {
            int a = 0;
#pragma unroll
            for (int o = 0; o < 8; o++) a |= (zs[o * 8 + tid] > 0.0f);
            actn[tid] = a;
        }
        __syncthreads();
        int b  = (blockIdx.x << 2) + (tid >> 6);
        int u4 = tid & 63;
#pragma unroll
        for (int n = 0; n < 8; n++) {
            if (!actn[n]) continue;
            size_t e = ((size_t)b * 8 + n) * 256 + u4 * 4;
            float4 v = *reinterpret_cast<const float4*>(X + e);
            __half2 h0 = __floats2half2_rn(v.x, v.y);
            __half2 h1 = __floats2half2_rn(v.z, v.w);
            uint2 w;
            w.x = *reinterpret_cast<uint32_t*>(&h0);
            w.y = *reinterpret_cast<uint32_t*>(&h1);
            *reinterpret_cast<uint2*>(g_xh + e) = w;
        }
        return;
    }

    // ---- W gate + transpose, open gates only ----
    __shared__ float tile[64][65];
    int blk = blockIdx.x - 2048;   // 0..1023
    int on = blk >> 4;
    int o = on >> 3, n = on & 7;
    int u0 = ((blk >> 2) & 3) * 64;
    int v0 = (blk & 3) * 64;
    float z = zs[o * 8 + n];
    if (z == 0.0f) return;

    const float* tb = T + (((size_t)(o * 8 + n) * 256 + u0) * 256 + v0);
#pragma unroll
    for (int i = 0; i < 16; i++) {
        int r = i * 4 + (tid >> 6);
        int c = tid & 63;
        tile[r][c] = tb[(size_t)r * 256 + c];
    }
    __syncthreads();

    __half* wb = g_wh + ((size_t)o * 256 + v0) * 2048 + n * 256 + u0;
#pragma unroll
    for (int i = 0; i < 16; i++) {
        int r = i * 4 + (tid >> 6);   // v-row
        int c = tid & 63;             // u-col
        wb[(size_t)r * 2048 + c] = __float2half_rn(tile[c][r] * z);
    }
}

// ===================== fp16 pipelined GEMM =====================
// Tile BM=64 x BN=128. Grid (16, 128): x = (o, n-half), y = m-tile.
// 128 threads = 4 warps (2m x 2n), warp tile 32x64. 2-stage cp.async.
__global__ __launch_bounds__(128)
void gemm_fp16(const float* __restrict__ alpha,
               const float* __restrict__ u_param,
               float* __restrict__ out) {
    extern __shared__ char smem[];
    const uint32_t sb = smem_u32(smem);
    __shared__ float zs[64];
    __shared__ int nlist_s[8];
    __shared__ int cnt_s;

    const int tid = threadIdx.x, lane = tid & 31, warp = tid >> 5;
    const int o  = blockIdx.x >> 1;
    const int n0 = (blockIdx.x & 1) * BN;
    const int m0 = blockIdx.y * BM;

    if (tid < 64) zs[tid] = gate_z(u_param, alpha, tid);
    __syncthreads();
    if (tid == 0) {
        int c = 0;
#pragma unroll
        for (int nn = 0; nn < 8; nn++)
            if (zs[o * 8 + nn] > 0.0f) nlist_s[c++] = nn;
        cnt_s = c;
    }
    __syncthreads();
    const int chunks = cnt_s * 4;     // 4 x BK=64 chunks per active n

    // ---- fast path: closed o -> coalesced write-through zeros ----
    if (chunks == 0) {
        float* base = out + ((size_t)m0 * O_ + o) * V_ + n0;
        const uint4 z4 = make_uint4(0u, 0u, 0u, 0u);
#pragma unroll
        for (int i = tid; i < 1024; i += 128) {       // 64 rows x 16 uint4
            int r = i >> 4, c = i & 15;
            __stwt(reinterpret_cast<uint4*>(base + (size_t)r * (O_ * V_)) + c, z4);
        }
        return;
    }

    const __half* Ag = g_xh + (size_t)m0 * K_;
    const __half* Bg = g_wh + ((size_t)o * V_ + n0) * K_;

    // cp.async per stage: A 512 ops (4/thread) + B 1024 ops (8/thread)
    auto issue = [&](int c) {
        const uint32_t so = (uint32_t)(c & 1) * STG_BYTES;
        const int k0 = (nlist_s[c >> 2] << 8) + ((c & 3) << 6);
#pragma unroll
        for (int i = 0; i < 4; i++) {
            int idx = tid + i * 128;
            int r = idx >> 3, cc = idx & 7;
            cpa16(sb + so + r * ROWB + cc * 16, Ag + (size_t)r * K_ + k0 + cc * 8);
        }
#pragma unroll
        for (int i = 0; i < 8; i++) {
            int idx = tid + i * 128;
            int r = idx >> 3, cc = idx & 7;
            cpa16(sb + so + A_BYTES + r * ROWB + cc * 16,
                  Bg + (size_t)r * K_ + k0 + cc * 8);
        }
    };

    const int mo = (warp >> 1) * 32;   // 2 warps in m
    const int no = (warp & 1) * 64;    // 2 warps in n
    uint32_t a_addr[2], b_addr[4];
    {
        const int arl = lane & 15;
        const int akh = (lane >> 4) & 1;
#pragma unroll
        for (int mf = 0; mf < 2; mf++)
            a_addr[mf] = sb + (mo + mf * 16 + arl) * ROWB + akh * 16;
        const int brl = (lane & 7) + ((lane >> 4) & 1) * 8;
        const int bkh = (lane >> 3) & 1;
#pragma unroll
        for (int p = 0; p < 4; p++)
            b_addr[p] = sb + A_BYTES + (no + p * 16 + brl) * ROWB + bkh * 16;
    }

    float acc[2][8][4];
#pragma unroll
    for (int i = 0; i < 2; i++)
#pragma unroll
        for (int j = 0; j < 8; j++)
#pragma unroll
            for (int k = 0; k < 4; k++) acc[i][j][k] = 0.0f;

    issue(0); CP_COMMIT();

    for (int c = 0; c < chunks; ++c) {
        if (c + 1 < chunks) issue(c + 1);
        CP_COMMIT();
        CP_WAIT1();               // group c complete (<=1 pending)
        __syncthreads();

        const uint32_t so = (uint32_t)(c & 1) * STG_BYTES;
#pragma unroll
        for (int ks = 0; ks < 4; ks++) {       // 4 k16 steps per BK=64
            const uint32_t kb = so + ks * 32;
            uint32_t a[2][4], b[4][4];
#pragma unroll
            for (int mf = 0; mf < 2; mf++) ldsm4(a[mf], a_addr[mf] + kb);
#pragma unroll
            for (int p = 0; p < 4; p++) ldsm4(b[p], b_addr[p] + kb);
#pragma unroll
            for (int mf = 0; mf < 2; mf++)
#pragma unroll
                for (int p = 0; p < 4; p++) {
                    mma16816(acc[mf][2 * p],     a[mf], b[p][0], b[p][1]);
                    mma16816(acc[mf][2 * p + 1], a[mf], b[p][2], b[p][3]);
                }
        }
        __syncthreads();          // stage c reused by issue(c+2) next iter
    }

    const int gid = lane >> 2, tig = lane & 3;
#pragma unroll
    for (int mf = 0; mf < 2; mf++) {
        const int brow = m0 + mo + mf * 16 + gid;
#pragma unroll
        for (int nb = 0; nb < 8; nb++) {
            const int v = n0 + no + nb * 8 + tig * 2;
            float* c = acc[mf][nb];
            __stwt(reinterpret_cast<float2*>(
                out + ((size_t)brow * O_ + o) * V_ + v), make_float2(c[0], c[1]));
            __stwt(reinterpret_cast<float2*>(
                out + ((size_t)(brow + 8) * O_ + o) * V_ + v), make_float2(c[2], c[3]));
        }
    }
}

// ===================== host =====================
extern "C" void kernel_launch(void* const* d_in, const int* in_sizes, int n_in,
                              void* d_out, int out_size) {
    const float* x = nullptr, *alpha = nullptr, *u = nullptr, *T = nullptr;
    for (int i = 0; i < n_in; i++) {
        switch (in_sizes[i]) {
            case 16777216: x     = (const float*)d_in[i]; break;
            case 1:        alpha = (const float*)d_in[i]; break;
            case 64:       u     = (const float*)d_in[i]; break;
            case 4194304:  T     = (const float*)d_in[i]; break;
        }
    }
    if (!x || !alpha || !u || !T) return;
    float* out = (float*)d_out;

    static bool attr_set = false;
    if (!attr_set) {
        cudaFuncSetAttribute(gemm_fp16, cudaFuncAttributeMaxDynamicSharedMemorySize,
                             SMEM_TOTAL);
        attr_set = true;
    }

    prep<<<3072, 256>>>(x, T, alpha, u);
    gemm_fp16<<<dim3(16, 128), 128, SMEM_TOTAL>>>(alpha, u, out);
}